// round 11
// baseline (speedup 1.0000x reference)
#include <cuda_runtime.h>
#include <cuda_fp16.h>
#include <stdint.h>
#include <math.h>

#define D_MODEL 1536
#define S_LEN   4096
#define T_LEN   154
#define N_BC    8
#define N_B     2
#define N_H     24
#define DH      64

// ---------------- scratch (device globals; no allocation allowed) ----------------
__device__ __half g_HSh [N_BC * S_LEN * D_MODEL];
__device__ __half g_EHSh[N_BC * T_LEN * D_MODEL];
__device__ __half g_Qh  [N_BC * S_LEN * D_MODEL];
__device__ __half g_Kh  [N_BC * T_LEN * D_MODEL];
__device__ __half g_Vh  [N_BC * T_LEN * D_MODEL];
__device__ __half g_AOh [N_BC * S_LEN * D_MODEL];
__device__ __half g_Wqh[D_MODEL * D_MODEL];
__device__ __half g_Wkh[D_MODEL * D_MODEL];
__device__ __half g_Wvh[D_MODEL * D_MODEL];
__device__ __half g_Woh[D_MODEL * D_MODEL];

// ================= helpers =================
__device__ __forceinline__ uint32_t smem_u32(const void* p) {
    uint32_t a;
    asm("{ .reg .u64 t; cvta.to.shared.u64 t, %1; cvt.u32.u64 %0, t; }" : "=r"(a) : "l"(p));
    return a;
}
__device__ __forceinline__ void ldm_x4(uint32_t* r, uint32_t addr) {
    asm volatile("ldmatrix.sync.aligned.m8n8.x4.shared.b16 {%0,%1,%2,%3}, [%4];"
        : "=r"(r[0]), "=r"(r[1]), "=r"(r[2]), "=r"(r[3]) : "r"(addr));
}
__device__ __forceinline__ void ldm_x4_t(uint32_t* r, uint32_t addr) {
    asm volatile("ldmatrix.sync.aligned.m8n8.x4.trans.shared.b16 {%0,%1,%2,%3}, [%4];"
        : "=r"(r[0]), "=r"(r[1]), "=r"(r[2]), "=r"(r[3]) : "r"(addr));
}
__device__ __forceinline__ void mma16816h(float* d, const uint32_t* a,
                                          uint32_t b0, uint32_t b1) {
    asm volatile(
        "mma.sync.aligned.m16n8k16.row.col.f32.f16.f16.f32 "
        "{%0,%1,%2,%3}, {%4,%5,%6,%7}, {%8,%9}, {%0,%1,%2,%3};"
        : "+f"(d[0]), "+f"(d[1]), "+f"(d[2]), "+f"(d[3])
        : "r"(a[0]), "r"(a[1]), "r"(a[2]), "r"(a[3]), "r"(b0), "r"(b1));
}
__device__ __forceinline__ void cp_async16(uint32_t dst, const void* src) {
    asm volatile("cp.async.cg.shared.global [%0], [%1], 16;" :: "r"(dst), "l"(src));
}
#define CP_COMMIT() asm volatile("cp.async.commit_group;" ::: "memory")
#define CP_WAIT(n)  asm volatile("cp.async.wait_group %0;" :: "n"(n) : "memory")

__device__ __forceinline__ uint32_t packh2(float a, float b) {
    __half2 h = __floats2half2_rn(a, b);
    return *(uint32_t*)&h;
}
__device__ __forceinline__ float ex2a(float x) {
    float y; asm("ex2.approx.f32 %0, %1;" : "=f"(y) : "f"(x)); return y;
}
__device__ __forceinline__ float rcpa(float x) {
    float y; asm("rcp.approx.f32 %0, %1;" : "=f"(y) : "f"(x)); return y;
}

// ================= fp32 -> fp16 convert =================
__global__ void f2h_kernel(const float* __restrict__ x, __half* __restrict__ y, int n4)
{
    int i = blockIdx.x * blockDim.x + threadIdx.x;
    if (i < n4) {
        float4 v = ((const float4*)x)[i];
        __half2* yp = (__half2*)y + i * 2;
        yp[0] = __floats2half2_rn(v.x, v.y);
        yp[1] = __floats2half2_rn(v.z, v.w);
    }
}

__global__ void f2h4_kernel(const float* __restrict__ x0, const float* __restrict__ x1,
                            const float* __restrict__ x2, const float* __restrict__ x3,
                            __half* __restrict__ y0, __half* __restrict__ y1,
                            __half* __restrict__ y2, __half* __restrict__ y3, int n4)
{
    const float* x; __half* y;
    switch (blockIdx.y) {
        case 0:  x = x0; y = y0; break;
        case 1:  x = x1; y = y1; break;
        case 2:  x = x2; y = y2; break;
        default: x = x3; y = y3; break;
    }
    int i = blockIdx.x * blockDim.x + threadIdx.x;
    if (i < n4) {
        float4 v = ((const float4*)x)[i];
        __half2* yp = (__half2*)y + i * 2;
        yp[0] = __floats2half2_rn(v.x, v.y);
        yp[1] = __floats2half2_rn(v.z, v.w);
    }
}

// ================= fp16 HGEMM: Y[M,N] = A[M,K] @ B[N,K]^T + bias ====================
// CTA 128x128, BK=64, 2-stage smem double buffer + double-buffered LDSM fragments.
#define LDA    72
#define ASTG   (128 * LDA)
#define STG2   (2 * ASTG)
#define NSTAGE 2
#define GEMM_SMEM_BYTES (NSTAGE * STG2 * 2)   // 73728

template<bool HOUT>
__global__ __launch_bounds__(256, 2)
void hgemm_bias(const __half* __restrict__ A, const __half* __restrict__ B,
                const float* __restrict__ bias, void* __restrict__ Yv,
                const __half* __restrict__ B2, const float* __restrict__ bias2,
                void* __restrict__ Yv2, int nx1,
                int M, int N, int K)
{
    extern __shared__ __half sm[];
    const uint32_t sbase = smem_u32(sm);
    const int tid  = threadIdx.x;
    const int wid  = tid >> 5;
    const int lane = tid & 31;

    const __half* Bp = B;
    const float*  bp = bias;
    void*         Yp = Yv;
    int bx = blockIdx.x;
    if (B2 != nullptr && bx >= nx1) { Bp = B2; bp = bias2; Yp = Yv2; bx -= nx1; }

    const int bm   = blockIdx.y * 128;
    const int bn   = bx * 128;
    const int wm   = wid & 3;
    const int wn   = wid >> 2;
    const int xrow = lane & 15;
    const int xk   = (lane >> 4) << 3;

    const int crow = tid >> 3;
    const int ccol = (tid & 7) << 3;
    const __half* aptr[4];
    const __half* bptr[4];
    uint32_t soff[4];
    #pragma unroll
    for (int t = 0; t < 4; ++t) {
        int row = crow + t * 32;
        aptr[t] = A  + (size_t)min(bm + row, M - 1) * K + ccol;
        bptr[t] = Bp + (size_t)(bn + row) * K + ccol;
        soff[t] = (uint32_t)(row * LDA + ccol) * 2;
    }

    float acc[2][8][4];
    #pragma unroll
    for (int i = 0; i < 2; ++i)
        #pragma unroll
        for (int j = 0; j < 8; ++j)
            #pragma unroll
            for (int q = 0; q < 4; ++q) acc[i][j][q] = 0.f;

    const int NIT = K / 64;   // 24

    auto issue = [&](int it) {
        const int s  = it & 1;
        const int k0 = it * 64;
        uint32_t sa = sbase + (uint32_t)s * STG2 * 2;
        uint32_t sb = sa + ASTG * 2;
        #pragma unroll
        for (int t = 0; t < 4; ++t) {
            cp_async16(sa + soff[t], aptr[t] + k0);
            cp_async16(sb + soff[t], bptr[t] + k0);
        }
    };

    issue(0); CP_COMMIT();

    // base smem offsets for this warp's fragments (k0 added per step)
    const uint32_t aoff0 = (uint32_t)((wm * 32 +      xrow) * LDA + xk) * 2;
    const uint32_t aoff1 = (uint32_t)((wm * 32 + 16 + xrow) * LDA + xk) * 2;

    for (int it = 0; it < NIT; ++it) {
        CP_WAIT(0);
        __syncthreads();
        if (it + 1 < NIT) { issue(it + 1); CP_COMMIT(); }

        const uint32_t sa = sbase + (uint32_t)(it & 1) * STG2 * 2;
        const uint32_t sb = sa + ASTG * 2;

        uint32_t af[2][2][4];     // [parity][mf][4]
        uint32_t bf[2][4][4];     // [parity][nf4][4]

        // preload kk = 0 fragments
        ldm_x4(af[0][0], sa + aoff0);
        ldm_x4(af[0][1], sa + aoff1);
        #pragma unroll
        for (int nf4 = 0; nf4 < 4; ++nf4)
            ldm_x4(bf[0][nf4], sb + (uint32_t)((wn * 64 + nf4 * 16 + xrow) * LDA + xk) * 2);

        #pragma unroll
        for (int kk = 0; kk < 4; ++kk) {
            const int cur = kk & 1;
            const int nxt = cur ^ 1;
            if (kk < 3) {   // prefetch kk+1 fragments while cur MMAs run
                const uint32_t k1 = (uint32_t)(kk + 1) * 32;   // 16 halfs * 2B
                ldm_x4(af[nxt][0], sa + aoff0 + k1);
                ldm_x4(af[nxt][1], sa + aoff1 + k1);
                #pragma unroll
                for (int nf4 = 0; nf4 < 4; ++nf4)
                    ldm_x4(bf[nxt][nf4],
                           sb + (uint32_t)((wn * 64 + nf4 * 16 + xrow) * LDA + xk) * 2 + k1);
            }
            #pragma unroll
            for (int nf4 = 0; nf4 < 4; ++nf4) {
                #pragma unroll
                for (int mf = 0; mf < 2; ++mf) {
                    mma16816h(acc[mf][nf4 * 2],     af[cur][mf], bf[cur][nf4][0], bf[cur][nf4][2]);
                    mma16816h(acc[mf][nf4 * 2 + 1], af[cur][mf], bf[cur][nf4][1], bf[cur][nf4][3]);
                }
            }
        }
    }
    __syncthreads();

    const int g  = lane >> 2;
    const int t2 = (lane & 3) << 1;
    #pragma unroll
    for (int mf = 0; mf < 2; ++mf) {
        int r0 = bm + wm * 32 + mf * 16 + g;
        #pragma unroll
        for (int nf = 0; nf < 8; ++nf) {
            int col = bn + wn * 64 + nf * 8 + t2;
            float bv0 = bp[col], bv1 = bp[col + 1];
            float v00 = acc[mf][nf][0] + bv0, v01 = acc[mf][nf][1] + bv1;
            float v10 = acc[mf][nf][2] + bv0, v11 = acc[mf][nf][3] + bv1;
            if (HOUT) {
                __half* Y = (__half*)Yp;
                if (r0 < M)     *(__half2*)(Y + (size_t)r0 * N + col)       = __floats2half2_rn(v00, v01);
                if (r0 + 8 < M) *(__half2*)(Y + (size_t)(r0 + 8) * N + col) = __floats2half2_rn(v10, v11);
            } else {
                float* Y = (float*)Yp;
                if (r0 < M)     *(float2*)(Y + (size_t)r0 * N + col)       = make_float2(v00, v01);
                if (r0 + 8 < M) *(float2*)(Y + (size_t)(r0 + 8) * N + col) = make_float2(v10, v11);
            }
        }
    }
}

// ================= register-softmax HMMA attention (dedup, e3-baseline) ===========
#define QST 72
#define KST 72
#define KV_MAT   (4 * 32 * KST * 2)              // 18432 B
#define KV_STAGE (2 * KV_MAT)                    // 36864 B (K + V)
#define ATTN_SMEM_BYTES (4 * 64 * QST * 2 + 2 * KV_STAGE)   // 110592

#define SM_SCALE 0.1803368801f

__global__ __launch_bounds__(128, 2)
void attn_reg(const __half* __restrict__ Q, const __half* __restrict__ K,
              const __half* __restrict__ V, __half* __restrict__ O)
{
    extern __shared__ char smemc[];
    __half* qb = (__half*)smemc;                 // [4][64][QST]
    const uint32_t qbu = smem_u32(qb);
    const uint32_t kvu = qbu + 4 * 64 * QST * 2;

    const int tid  = threadIdx.x;
    const int wid  = tid >> 5;
    const int lane = tid & 31;
    const int b    = blockIdx.z;
    const int h    = blockIdx.y;
    const int s0   = blockIdx.x * 64;

    const int sbase = wid * 16;
    const int xrow  = lane & 15;
    const int xk    = (lane >> 4) << 3;
    const int g     = lane >> 2;
    const int q2    = (lane & 3) << 1;

    #pragma unroll
    for (int it = 0; it < 16; ++it) {
        int i  = tid + it * 128;
        int cc = i >> 9, r = i & 511, si = r >> 3, d8 = (r & 7) << 3;
        const __half* gp = Q + ((size_t)(cc * N_B + b) * S_LEN + s0 + si) * D_MODEL + h * DH + d8;
        *(uint4*)(qb + (cc * 64 + si) * QST + d8) = *(const uint4*)gp;
    }

    const int NCH = (T_LEN + 31) / 32;   // 5

    auto issue = [&](int ch) {
        const int t0 = ch * 32;
        const uint32_t st = kvu + (uint32_t)(ch & 1) * KV_STAGE;
        #pragma unroll
        for (int it = 0; it < 8; ++it) {
            int i  = tid + it * 128;
            int cc = i >> 8, r = i & 255, tj = r >> 3, d8 = (r & 7) << 3;
            int t = min(t0 + tj, T_LEN - 1);
            size_t go = ((size_t)(cc * N_B + b) * T_LEN + t) * D_MODEL + h * DH + d8;
            uint32_t so = (uint32_t)((cc * 32 + tj) * KST + d8) * 2;
            cp_async16(st + so, K + go);
            cp_async16(st + KV_MAT + so, V + go);
        }
    };

    issue(0); CP_COMMIT();
    issue(1); CP_COMMIT();

    float oacc[4][8][4];
    #pragma unroll
    for (int c = 0; c < 4; ++c)
        #pragma unroll
        for (int j = 0; j < 8; ++j)
            #pragma unroll
            for (int e = 0; e < 4; ++e) oacc[c][j][e] = 0.f;
    float rsum[2][4];
    #pragma unroll
    for (int r = 0; r < 2; ++r)
        #pragma unroll
        for (int c = 0; c < 4; ++c) rsum[r][c] = 0.f;

    for (int ch = 0; ch < NCH; ++ch) {
        if (ch == NCH - 1) { CP_WAIT(0); } else { CP_WAIT(1); }
        __syncthreads();

        const uint32_t kbu = kvu + (uint32_t)(ch & 1) * KV_STAGE;
        const uint32_t vbu = kbu + KV_MAT;

        float sacc[4][4][4];
        #pragma unroll
        for (int c = 0; c < 4; ++c)
            #pragma unroll
            for (int j = 0; j < 4; ++j)
                #pragma unroll
                for (int e = 0; e < 4; ++e) sacc[c][j][e] = 0.f;

        #pragma unroll
        for (int c = 0; c < 4; ++c) {
            #pragma unroll
            for (int kk = 0; kk < 4; ++kk) {
                uint32_t af[4];
                ldm_x4(af, qbu + (uint32_t)((c * 64 + sbase + xrow) * QST + kk * 16 + xk) * 2);
                #pragma unroll
                for (int nf16 = 0; nf16 < 2; ++nf16) {
                    uint32_t bf[4];
                    ldm_x4(bf, kbu + (uint32_t)((c * 32 + nf16 * 16 + xrow) * KST + kk * 16 + xk) * 2);
                    mma16816h(sacc[c][nf16 * 2],     af, bf[0], bf[2]);
                    mma16816h(sacc[c][nf16 * 2 + 1], af, bf[1], bf[3]);
                }
            }
        }

        #pragma unroll
        for (int kk = 0; kk < 2; ++kk) {
            uint32_t wf[4][4];
            #pragma unroll
            for (int jh = 0; jh < 2; ++jh) {
                const int j = kk * 2 + jh;
                float wt[4][4];
                #pragma unroll
                for (int e = 0; e < 4; ++e) {
                    int col = ch * 32 + j * 8 + q2 + (e & 1);
                    float t3 = sacc[3][j][e] * SM_SCALE;
                    float e0 = ex2a(fmaf(sacc[0][j][e], SM_SCALE, -t3));
                    float e1 = ex2a(fmaf(sacc[1][j][e], SM_SCALE, -t3));
                    float e2 = ex2a(fmaf(sacc[2][j][e], SM_SCALE, -t3));
                    float inv = (col < T_LEN) ? rcpa(e0 + e1 + e2 + 1.f) : 0.f;
                    e0 *= inv; e1 *= inv; e2 *= inv;
                    int rr = e >> 1;
                    rsum[rr][0] += e0; rsum[rr][1] += e1;
                    rsum[rr][2] += e2; rsum[rr][3] += inv;
                    wt[0][e] = e0; wt[1][e] = e1; wt[2][e] = e2; wt[3][e] = inv;
                }
                #pragma unroll
                for (int c = 0; c < 4; ++c) {
                    wf[c][jh * 2 + 0] = packh2(wt[c][0], wt[c][1]);
                    wf[c][jh * 2 + 1] = packh2(wt[c][2], wt[c][3]);
                }
            }
            #pragma unroll
            for (int c = 0; c < 4; ++c) {
                #pragma unroll
                for (int nf16 = 0; nf16 < 4; ++nf16) {
                    uint32_t bf[4];
                    ldm_x4_t(bf, vbu + (uint32_t)((c * 32 + kk * 16 + xrow) * KST + nf16 * 16 + xk) * 2);
                    mma16816h(oacc[c][nf16 * 2],     wf[c], bf[0], bf[1]);
                    mma16816h(oacc[c][nf16 * 2 + 1], wf[c], bf[2], bf[3]);
                }
            }
        }
        __syncthreads();
        if (ch + 2 < NCH) { issue(ch + 2); CP_COMMIT(); }
    }

    #pragma unroll
    for (int x = 1; x <= 2; x <<= 1)
        #pragma unroll
        for (int r = 0; r < 2; ++r)
            #pragma unroll
            for (int c = 0; c < 4; ++c)
                rsum[r][c] += __shfl_xor_sync(0xffffffffu, rsum[r][c], x);

    #pragma unroll
    for (int c = 0; c < 4; ++c) {
        float inv0 = 1.f / (rsum[0][c] + 1e-8f);
        float inv1 = 1.f / (rsum[1][c] + 1e-8f);
        int row0 = s0 + sbase + g;
        __half* gp0 = O + ((size_t)(c * N_B + b) * S_LEN + row0) * D_MODEL + h * DH + q2;
        __half* gp1 = gp0 + (size_t)8 * D_MODEL;
        #pragma unroll
        for (int j = 0; j < 8; ++j) {
            *(__half2*)(gp0 + j * 8) = __floats2half2_rn(oacc[c][j][0] * inv0, oacc[c][j][1] * inv0);
            *(__half2*)(gp1 + j * 8) = __floats2half2_rn(oacc[c][j][2] * inv1, oacc[c][j][3] * inv1);
        }
    }
}

// ---------------- launch ----------------
extern "C" void kernel_launch(void* const* d_in, const int* in_sizes, int n_in,
                              void* d_out, int out_size)
{
    const float* HS  = (const float*)d_in[0];
    const float* EHS = (const float*)d_in[1];
    const float* Wq  = (const float*)d_in[2];
    const float* bq  = (const float*)d_in[3];
    const float* Wk  = (const float*)d_in[4];
    const float* bk  = (const float*)d_in[5];
    const float* Wv  = (const float*)d_in[6];
    const float* bv  = (const float*)d_in[7];
    const float* Wo  = (const float*)d_in[8];
    const float* bo  = (const float*)d_in[9];
    float* out = (float*)d_out;

    __half *pHSh, *pEHSh, *pQh, *pKh, *pVh, *pAOh, *pWqh, *pWkh, *pWvh, *pWoh;
    cudaGetSymbolAddress((void**)&pHSh,  g_HSh);
    cudaGetSymbolAddress((void**)&pEHSh, g_EHSh);
    cudaGetSymbolAddress((void**)&pQh,   g_Qh);
    cudaGetSymbolAddress((void**)&pKh,   g_Kh);
    cudaGetSymbolAddress((void**)&pVh,   g_Vh);
    cudaGetSymbolAddress((void**)&pAOh,  g_AOh);
    cudaGetSymbolAddress((void**)&pWqh,  g_Wqh);
    cudaGetSymbolAddress((void**)&pWkh,  g_Wkh);
    cudaGetSymbolAddress((void**)&pWvh,  g_Wvh);
    cudaGetSymbolAddress((void**)&pWoh,  g_Woh);

    cudaFuncSetAttribute(hgemm_bias<true>,  cudaFuncAttributeMaxDynamicSharedMemorySize, GEMM_SMEM_BYTES);
    cudaFuncSetAttribute(hgemm_bias<false>, cudaFuncAttributeMaxDynamicSharedMemorySize, GEMM_SMEM_BYTES);
    cudaFuncSetAttribute(attn_reg, cudaFuncAttributeMaxDynamicSharedMemorySize, ATTN_SMEM_BYTES);

    const int nHS = N_BC * S_LEN * D_MODEL / 4;
    const int nEH = N_BC * T_LEN * D_MODEL / 4;
    const int nW  = D_MODEL * D_MODEL / 4;
    f2h_kernel<<<(nHS + 255) / 256, 256>>>(HS,  pHSh,  nHS);
    f2h_kernel<<<(nEH + 255) / 256, 256>>>(EHS, pEHSh, nEH);
    f2h4_kernel<<<dim3((nW + 255) / 256, 4), 256>>>(Wq, Wk, Wv, Wo,
                                                    pWqh, pWkh, pWvh, pWoh, nW);

    dim3 gblk(256);
    // Q projection (fp16 out)
    hgemm_bias<true><<<dim3(12, 256), gblk, GEMM_SMEM_BYTES>>>(
        pHSh, pWqh, bq, pQh, nullptr, nullptr, nullptr, 0,
        N_BC * S_LEN, D_MODEL, D_MODEL);
    // merged K + V projections (fp16 out)
    hgemm_bias<true><<<dim3(24, 10), gblk, GEMM_SMEM_BYTES>>>(
        pEHSh, pWkh, bk, pKh, pWvh, bv, pVh, 12,
        N_BC * T_LEN, D_MODEL, D_MODEL);
    // dedup register-softmax HMMA attention (s-tile 64)
    attn_reg<<<dim3(S_LEN / 64, N_H, N_B), 128, ATTN_SMEM_BYTES>>>(pQh, pKh, pVh, pAOh);
    // output projection (fp32 output into d_out)
    hgemm_bias<false><<<dim3(12, 256), gblk, GEMM_SMEM_BYTES>>>(
        pAOh, pWoh, bo, out, nullptr, nullptr, nullptr, 0,
        N_BC * S_LEN, D_MODEL, D_MODEL);
}

// round 12
// speedup vs baseline: 1.0101x; 1.0101x over previous
#include <cuda_runtime.h>
#include <cuda_fp16.h>
#include <stdint.h>
#include <math.h>

#define D_MODEL 1536
#define S_LEN   4096
#define T_LEN   154
#define N_BC    8
#define N_B     2
#define N_H     24
#define DH      64

// ---------------- scratch (device globals; no allocation allowed) ----------------
__device__ __half g_HSh [N_BC * S_LEN * D_MODEL];
__device__ __half g_EHSh[N_BC * T_LEN * D_MODEL];
__device__ __half g_Qh  [N_BC * S_LEN * D_MODEL];
__device__ __half g_Kh  [N_BC * T_LEN * D_MODEL];
__device__ __half g_Vh  [N_BC * T_LEN * D_MODEL];
__device__ __half g_AOh [N_BC * S_LEN * D_MODEL];
__device__ __half g_Wqh[D_MODEL * D_MODEL];
__device__ __half g_Wkh[D_MODEL * D_MODEL];
__device__ __half g_Wvh[D_MODEL * D_MODEL];
__device__ __half g_Woh[D_MODEL * D_MODEL];

// ================= helpers =================
__device__ __forceinline__ uint32_t smem_u32(const void* p) {
    uint32_t a;
    asm("{ .reg .u64 t; cvta.to.shared.u64 t, %1; cvt.u32.u64 %0, t; }" : "=r"(a) : "l"(p));
    return a;
}
__device__ __forceinline__ void ldm_x4(uint32_t* r, uint32_t addr) {
    asm volatile("ldmatrix.sync.aligned.m8n8.x4.shared.b16 {%0,%1,%2,%3}, [%4];"
        : "=r"(r[0]), "=r"(r[1]), "=r"(r[2]), "=r"(r[3]) : "r"(addr));
}
__device__ __forceinline__ void ldm_x4_t(uint32_t* r, uint32_t addr) {
    asm volatile("ldmatrix.sync.aligned.m8n8.x4.trans.shared.b16 {%0,%1,%2,%3}, [%4];"
        : "=r"(r[0]), "=r"(r[1]), "=r"(r[2]), "=r"(r[3]) : "r"(addr));
}
__device__ __forceinline__ void mma16816h(float* d, const uint32_t* a,
                                          uint32_t b0, uint32_t b1) {
    asm volatile(
        "mma.sync.aligned.m16n8k16.row.col.f32.f16.f16.f32 "
        "{%0,%1,%2,%3}, {%4,%5,%6,%7}, {%8,%9}, {%0,%1,%2,%3};"
        : "+f"(d[0]), "+f"(d[1]), "+f"(d[2]), "+f"(d[3])
        : "r"(a[0]), "r"(a[1]), "r"(a[2]), "r"(a[3]), "r"(b0), "r"(b1));
}
__device__ __forceinline__ void cp_async16(uint32_t dst, const void* src) {
    asm volatile("cp.async.cg.shared.global [%0], [%1], 16;" :: "r"(dst), "l"(src));
}
#define CP_COMMIT() asm volatile("cp.async.commit_group;" ::: "memory")
#define CP_WAIT(n)  asm volatile("cp.async.wait_group %0;" :: "n"(n) : "memory")

__device__ __forceinline__ uint32_t packh2(float a, float b) {
    __half2 h = __floats2half2_rn(a, b);
    return *(uint32_t*)&h;
}
__device__ __forceinline__ float ex2a(float x) {
    float y; asm("ex2.approx.f32 %0, %1;" : "=f"(y) : "f"(x)); return y;
}
__device__ __forceinline__ float rcpa(float x) {
    float y; asm("rcp.approx.f32 %0, %1;" : "=f"(y) : "f"(x)); return y;
}

// ================= fp32 -> fp16 convert =================
__global__ void f2h_kernel(const float* __restrict__ x, __half* __restrict__ y, int n4)
{
    int i = blockIdx.x * blockDim.x + threadIdx.x;
    if (i < n4) {
        float4 v = ((const float4*)x)[i];
        __half2* yp = (__half2*)y + i * 2;
        yp[0] = __floats2half2_rn(v.x, v.y);
        yp[1] = __floats2half2_rn(v.z, v.w);
    }
}

__global__ void f2h4_kernel(const float* __restrict__ x0, const float* __restrict__ x1,
                            const float* __restrict__ x2, const float* __restrict__ x3,
                            __half* __restrict__ y0, __half* __restrict__ y1,
                            __half* __restrict__ y2, __half* __restrict__ y3, int n4)
{
    const float* x; __half* y;
    switch (blockIdx.y) {
        case 0:  x = x0; y = y0; break;
        case 1:  x = x1; y = y1; break;
        case 2:  x = x2; y = y2; break;
        default: x = x3; y = y3; break;
    }
    int i = blockIdx.x * blockDim.x + threadIdx.x;
    if (i < n4) {
        float4 v = ((const float4*)x)[i];
        __half2* yp = (__half2*)y + i * 2;
        yp[0] = __floats2half2_rn(v.x, v.y);
        yp[1] = __floats2half2_rn(v.z, v.w);
    }
}

// ================= fp16 GEMM core: 128x128 CTA, 128 threads, warp tile 64x64 =======
// BK=64, 2-stage smem double buffer. A/B each LDSM-loaded only 2x per CTA (vs 2x/4x).
#define LDA    72
#define ASTG   (128 * LDA)
#define STG2   (2 * ASTG)
#define GEMM_SMEM_BYTES (2 * STG2 * 2)   // 73728

template<bool HOUT>
__device__ __forceinline__ void gemm_core(
    const __half* __restrict__ A, const __half* __restrict__ B,
    const float* __restrict__ bias, void* __restrict__ Yv,
    int M, int N, int K, int bm, int bn, char* smemc)
{
    const uint32_t sbase = smem_u32(smemc);
    const int tid  = threadIdx.x;
    const int wid  = tid >> 5;
    const int lane = tid & 31;
    const int wm   = wid & 1;          // 64-row half
    const int wn   = wid >> 1;         // 64-col half
    const int xrow = lane & 15;
    const int xk   = (lane >> 4) << 3;

    // loader: 128 threads, 8 rows-strides of 16; 8 A-chunks + 8 B-chunks of 16B/stage
    const int crow = tid >> 3;              // 0..15
    const int ccol = (tid & 7) << 3;        // 0..56

    float acc[4][8][4];
    #pragma unroll
    for (int i = 0; i < 4; ++i)
        #pragma unroll
        for (int j = 0; j < 8; ++j)
            #pragma unroll
            for (int q = 0; q < 4; ++q) acc[i][j][q] = 0.f;

    const int NIT = K / 64;   // 24

    auto issue = [&](int it) {
        const int s  = it & 1;
        const int k0 = it * 64;
        uint32_t sa = sbase + (uint32_t)s * STG2 * 2;
        uint32_t sb = sa + ASTG * 2;
        #pragma unroll
        for (int t = 0; t < 8; ++t) {
            int row = crow + t * 16;
            int gr  = min(bm + row, M - 1);
            uint32_t so = (uint32_t)(row * LDA + ccol) * 2;
            cp_async16(sa + so, A + (size_t)gr * K + k0 + ccol);
            cp_async16(sb + so, B + (size_t)(bn + row) * K + k0 + ccol);
        }
    };

    issue(0); CP_COMMIT();

    for (int it = 0; it < NIT; ++it) {
        CP_WAIT(0);
        __syncthreads();
        if (it + 1 < NIT) { issue(it + 1); CP_COMMIT(); }

        const uint32_t sa = sbase + (uint32_t)(it & 1) * STG2 * 2;
        const uint32_t sb = sa + ASTG * 2;

        #pragma unroll
        for (int kk = 0; kk < 4; ++kk) {
            const int k0 = kk * 16;
            uint32_t af[4][4];
            #pragma unroll
            for (int mf = 0; mf < 4; ++mf)
                ldm_x4(af[mf], sa + (uint32_t)((wm * 64 + mf * 16 + xrow) * LDA + k0 + xk) * 2);
            uint32_t bf[4][4];
            #pragma unroll
            for (int nf4 = 0; nf4 < 4; ++nf4)
                ldm_x4(bf[nf4], sb + (uint32_t)((wn * 64 + nf4 * 16 + xrow) * LDA + k0 + xk) * 2);
            #pragma unroll
            for (int nf4 = 0; nf4 < 4; ++nf4) {
                #pragma unroll
                for (int mf = 0; mf < 4; ++mf) {
                    mma16816h(acc[mf][nf4 * 2],     af[mf], bf[nf4][0], bf[nf4][2]);
                    mma16816h(acc[mf][nf4 * 2 + 1], af[mf], bf[nf4][1], bf[nf4][3]);
                }
            }
        }
    }

    const int g  = lane >> 2;
    const int t2 = (lane & 3) << 1;
    #pragma unroll
    for (int mf = 0; mf < 4; ++mf) {
        int r0 = bm + wm * 64 + mf * 16 + g;
        #pragma unroll
        for (int nf = 0; nf < 8; ++nf) {
            int col = bn + wn * 64 + nf * 8 + t2;
            float bv0 = bias[col], bv1 = bias[col + 1];
            float v00 = acc[mf][nf][0] + bv0, v01 = acc[mf][nf][1] + bv1;
            float v10 = acc[mf][nf][2] + bv0, v11 = acc[mf][nf][3] + bv1;
            if (HOUT) {
                __half* Y = (__half*)Yv;
                if (r0 < M)     *(__half2*)(Y + (size_t)r0 * N + col)       = __floats2half2_rn(v00, v01);
                if (r0 + 8 < M) *(__half2*)(Y + (size_t)(r0 + 8) * N + col) = __floats2half2_rn(v10, v11);
            } else {
                float* Y = (float*)Yv;
                if (r0 < M)     *(float2*)(Y + (size_t)r0 * N + col)       = make_float2(v00, v01);
                if (r0 + 8 < M) *(float2*)(Y + (size_t)(r0 + 8) * N + col) = make_float2(v10, v11);
            }
        }
    }
}

// merged Q + K + V projections in one launch (3312 CTAs)
#define QCTAS  3072           // 256 m-tiles x 12 n-tiles
#define KVCTAS 120            // 10 m-tiles x 12 n-tiles each

__global__ __launch_bounds__(128, 2)
void qkv_gemm(const __half* __restrict__ HSh, const __half* __restrict__ EHSh,
              const __half* __restrict__ Wq, const float* __restrict__ bq, __half* __restrict__ Qh,
              const __half* __restrict__ Wk, const float* __restrict__ bk, __half* __restrict__ Kh,
              const __half* __restrict__ Wv, const float* __restrict__ bv, __half* __restrict__ Vh)
{
    extern __shared__ char smemc[];
    int id = blockIdx.x;
    const __half* A; const __half* B; const float* bias; __half* Y; int M, bm, bn;
    if (id < QCTAS) {
        A = HSh; B = Wq; bias = bq; Y = Qh; M = N_BC * S_LEN;
        bm = (id / 12) * 128; bn = (id % 12) * 128;
    } else if (id < QCTAS + KVCTAS) {
        int r = id - QCTAS;
        A = EHSh; B = Wk; bias = bk; Y = Kh; M = N_BC * T_LEN;
        bm = (r / 12) * 128; bn = (r % 12) * 128;
    } else {
        int r = id - QCTAS - KVCTAS;
        A = EHSh; B = Wv; bias = bv; Y = Vh; M = N_BC * T_LEN;
        bm = (r / 12) * 128; bn = (r % 12) * 128;
    }
    gemm_core<true>(A, B, bias, Y, M, D_MODEL, D_MODEL, bm, bn, smemc);
}

__global__ __launch_bounds__(128, 2)
void o_gemm(const __half* __restrict__ A, const __half* __restrict__ B,
            const float* __restrict__ bias, float* __restrict__ Y)
{
    extern __shared__ char smemc[];
    int id = blockIdx.x;
    gemm_core<false>(A, B, bias, Y, N_BC * S_LEN, D_MODEL, D_MODEL,
                     (id / 12) * 128, (id % 12) * 128, smemc);
}

// ================= register-softmax HMMA attention (dedup, e3-baseline) ===========
#define QST 72
#define KST 72
#define KV_MAT   (4 * 32 * KST * 2)              // 18432 B
#define KV_STAGE (2 * KV_MAT)                    // 36864 B (K + V)
#define ATTN_SMEM_BYTES (4 * 64 * QST * 2 + 2 * KV_STAGE)   // 110592

#define SM_SCALE 0.1803368801f

__global__ __launch_bounds__(128, 2)
void attn_reg(const __half* __restrict__ Q, const __half* __restrict__ K,
              const __half* __restrict__ V, __half* __restrict__ O)
{
    extern __shared__ char smemc[];
    __half* qb = (__half*)smemc;                 // [4][64][QST]
    const uint32_t qbu = smem_u32(qb);
    const uint32_t kvu = qbu + 4 * 64 * QST * 2;

    const int tid  = threadIdx.x;
    const int wid  = tid >> 5;
    const int lane = tid & 31;
    const int b    = blockIdx.z;
    const int h    = blockIdx.y;
    const int s0   = blockIdx.x * 64;

    const int sbase = wid * 16;
    const int xrow  = lane & 15;
    const int xk    = (lane >> 4) << 3;
    const int g     = lane >> 2;
    const int q2    = (lane & 3) << 1;

    #pragma unroll
    for (int it = 0; it < 16; ++it) {
        int i  = tid + it * 128;
        int cc = i >> 9, r = i & 511, si = r >> 3, d8 = (r & 7) << 3;
        const __half* gp = Q + ((size_t)(cc * N_B + b) * S_LEN + s0 + si) * D_MODEL + h * DH + d8;
        *(uint4*)(qb + (cc * 64 + si) * QST + d8) = *(const uint4*)gp;
    }

    const int NCH = (T_LEN + 31) / 32;   // 5

    auto issue = [&](int ch) {
        const int t0 = ch * 32;
        const uint32_t st = kvu + (uint32_t)(ch & 1) * KV_STAGE;
        #pragma unroll
        for (int it = 0; it < 8; ++it) {
            int i  = tid + it * 128;
            int cc = i >> 8, r = i & 255, tj = r >> 3, d8 = (r & 7) << 3;
            int t = min(t0 + tj, T_LEN - 1);
            size_t go = ((size_t)(cc * N_B + b) * T_LEN + t) * D_MODEL + h * DH + d8;
            uint32_t so = (uint32_t)((cc * 32 + tj) * KST + d8) * 2;
            cp_async16(st + so, K + go);
            cp_async16(st + KV_MAT + so, V + go);
        }
    };

    issue(0); CP_COMMIT();
    issue(1); CP_COMMIT();

    float oacc[4][8][4];
    #pragma unroll
    for (int c = 0; c < 4; ++c)
        #pragma unroll
        for (int j = 0; j < 8; ++j)
            #pragma unroll
            for (int e = 0; e < 4; ++e) oacc[c][j][e] = 0.f;
    float rsum[2][4];
    #pragma unroll
    for (int r = 0; r < 2; ++r)
        #pragma unroll
        for (int c = 0; c < 4; ++c) rsum[r][c] = 0.f;

    for (int ch = 0; ch < NCH; ++ch) {
        if (ch == NCH - 1) { CP_WAIT(0); } else { CP_WAIT(1); }
        __syncthreads();

        const uint32_t kbu = kvu + (uint32_t)(ch & 1) * KV_STAGE;
        const uint32_t vbu = kbu + KV_MAT;

        float sacc[4][4][4];
        #pragma unroll
        for (int c = 0; c < 4; ++c)
            #pragma unroll
            for (int j = 0; j < 4; ++j)
                #pragma unroll
                for (int e = 0; e < 4; ++e) sacc[c][j][e] = 0.f;

        #pragma unroll
        for (int c = 0; c < 4; ++c) {
            #pragma unroll
            for (int kk = 0; kk < 4; ++kk) {
                uint32_t af[4];
                ldm_x4(af, qbu + (uint32_t)((c * 64 + sbase + xrow) * QST + kk * 16 + xk) * 2);
                #pragma unroll
                for (int nf16 = 0; nf16 < 2; ++nf16) {
                    uint32_t bf[4];
                    ldm_x4(bf, kbu + (uint32_t)((c * 32 + nf16 * 16 + xrow) * KST + kk * 16 + xk) * 2);
                    mma16816h(sacc[c][nf16 * 2],     af, bf[0], bf[2]);
                    mma16816h(sacc[c][nf16 * 2 + 1], af, bf[1], bf[3]);
                }
            }
        }

        #pragma unroll
        for (int kk = 0; kk < 2; ++kk) {
            uint32_t wf[4][4];
            #pragma unroll
            for (int jh = 0; jh < 2; ++jh) {
                const int j = kk * 2 + jh;
                float wt[4][4];
                #pragma unroll
                for (int e = 0; e < 4; ++e) {
                    int col = ch * 32 + j * 8 + q2 + (e & 1);
                    float t3 = sacc[3][j][e] * SM_SCALE;
                    float e0 = ex2a(fmaf(sacc[0][j][e], SM_SCALE, -t3));
                    float e1 = ex2a(fmaf(sacc[1][j][e], SM_SCALE, -t3));
                    float e2 = ex2a(fmaf(sacc[2][j][e], SM_SCALE, -t3));
                    float inv = (col < T_LEN) ? rcpa(e0 + e1 + e2 + 1.f) : 0.f;
                    e0 *= inv; e1 *= inv; e2 *= inv;
                    int rr = e >> 1;
                    rsum[rr][0] += e0; rsum[rr][1] += e1;
                    rsum[rr][2] += e2; rsum[rr][3] += inv;
                    wt[0][e] = e0; wt[1][e] = e1; wt[2][e] = e2; wt[3][e] = inv;
                }
                #pragma unroll
                for (int c = 0; c < 4; ++c) {
                    wf[c][jh * 2 + 0] = packh2(wt[c][0], wt[c][1]);
                    wf[c][jh * 2 + 1] = packh2(wt[c][2], wt[c][3]);
                }
            }
            #pragma unroll
            for (int c = 0; c < 4; ++c) {
                #pragma unroll
                for (int nf16 = 0; nf16 < 4; ++nf16) {
                    uint32_t bf[4];
                    ldm_x4_t(bf, vbu + (uint32_t)((c * 32 + kk * 16 + xrow) * KST + nf16 * 16 + xk) * 2);
                    mma16816h(oacc[c][nf16 * 2],     wf[c], bf[0], bf[1]);
                    mma16816h(oacc[c][nf16 * 2 + 1], wf[c], bf[2], bf[3]);
                }
            }
        }
        __syncthreads();
        if (ch + 2 < NCH) { issue(ch + 2); CP_COMMIT(); }
    }

    #pragma unroll
    for (int x = 1; x <= 2; x <<= 1)
        #pragma unroll
        for (int r = 0; r < 2; ++r)
            #pragma unroll
            for (int c = 0; c < 4; ++c)
                rsum[r][c] += __shfl_xor_sync(0xffffffffu, rsum[r][c], x);

    #pragma unroll
    for (int c = 0; c < 4; ++c) {
        float inv0 = 1.f / (rsum[0][c] + 1e-8f);
        float inv1 = 1.f / (rsum[1][c] + 1e-8f);
        int row0 = s0 + sbase + g;
        __half* gp0 = O + ((size_t)(c * N_B + b) * S_LEN + row0) * D_MODEL + h * DH + q2;
        __half* gp1 = gp0 + (size_t)8 * D_MODEL;
        #pragma unroll
        for (int j = 0; j < 8; ++j) {
            *(__half2*)(gp0 + j * 8) = __floats2half2_rn(oacc[c][j][0] * inv0, oacc[c][j][1] * inv0);
            *(__half2*)(gp1 + j * 8) = __floats2half2_rn(oacc[c][j][2] * inv1, oacc[c][j][3] * inv1);
        }
    }
}

// ---------------- launch ----------------
extern "C" void kernel_launch(void* const* d_in, const int* in_sizes, int n_in,
                              void* d_out, int out_size)
{
    const float* HS  = (const float*)d_in[0];
    const float* EHS = (const float*)d_in[1];
    const float* Wq  = (const float*)d_in[2];
    const float* bq  = (const float*)d_in[3];
    const float* Wk  = (const float*)d_in[4];
    const float* bk  = (const float*)d_in[5];
    const float* Wv  = (const float*)d_in[6];
    const float* bv  = (const float*)d_in[7];
    const float* Wo  = (const float*)d_in[8];
    const float* bo  = (const float*)d_in[9];
    float* out = (float*)d_out;

    __half *pHSh, *pEHSh, *pQh, *pKh, *pVh, *pAOh, *pWqh, *pWkh, *pWvh, *pWoh;
    cudaGetSymbolAddress((void**)&pHSh,  g_HSh);
    cudaGetSymbolAddress((void**)&pEHSh, g_EHSh);
    cudaGetSymbolAddress((void**)&pQh,   g_Qh);
    cudaGetSymbolAddress((void**)&pKh,   g_Kh);
    cudaGetSymbolAddress((void**)&pVh,   g_Vh);
    cudaGetSymbolAddress((void**)&pAOh,  g_AOh);
    cudaGetSymbolAddress((void**)&pWqh,  g_Wqh);
    cudaGetSymbolAddress((void**)&pWkh,  g_Wkh);
    cudaGetSymbolAddress((void**)&pWvh,  g_Wvh);
    cudaGetSymbolAddress((void**)&pWoh,  g_Woh);

    cudaFuncSetAttribute(qkv_gemm, cudaFuncAttributeMaxDynamicSharedMemorySize, GEMM_SMEM_BYTES);
    cudaFuncSetAttribute(o_gemm,   cudaFuncAttributeMaxDynamicSharedMemorySize, GEMM_SMEM_BYTES);
    cudaFuncSetAttribute(attn_reg, cudaFuncAttributeMaxDynamicSharedMemorySize, ATTN_SMEM_BYTES);

    const int nHS = N_BC * S_LEN * D_MODEL / 4;
    const int nEH = N_BC * T_LEN * D_MODEL / 4;
    const int nW  = D_MODEL * D_MODEL / 4;
    f2h_kernel<<<(nHS + 255) / 256, 256>>>(HS,  pHSh,  nHS);
    f2h_kernel<<<(nEH + 255) / 256, 256>>>(EHS, pEHSh, nEH);
    f2h4_kernel<<<dim3((nW + 255) / 256, 4), 256>>>(Wq, Wk, Wv, Wo,
                                                    pWqh, pWkh, pWvh, pWoh, nW);

    // merged Q + K + V projections (fp16 out), one launch
    qkv_gemm<<<QCTAS + 2 * KVCTAS, 128, GEMM_SMEM_BYTES>>>(
        pHSh, pEHSh, pWqh, bq, pQh, pWkh, bk, pKh, pWvh, bv, pVh);
    // dedup register-softmax HMMA attention (s-tile 64)
    attn_reg<<<dim3(S_LEN / 64, N_H, N_B), 128, ATTN_SMEM_BYTES>>>(pQh, pKh, pVh, pAOh);
    // output projection (fp32 output into d_out)
    o_gemm<<<QCTAS, 128, GEMM_SMEM_BYTES>>>(pAOh, pWoh, bo, out);
}

// round 13
// speedup vs baseline: 1.0282x; 1.0179x over previous
#include <cuda_runtime.h>
#include <cuda_fp16.h>
#include <stdint.h>
#include <math.h>

#define D_MODEL 1536
#define S_LEN   4096
#define T_LEN   154
#define N_BC    8
#define N_B     2
#define N_H     24
#define DH      64

// ---------------- scratch (device globals; no allocation allowed) ----------------
__device__ __half g_HSh [N_BC * S_LEN * D_MODEL];
__device__ __half g_EHSh[N_BC * T_LEN * D_MODEL];
__device__ __half g_Qh  [N_BC * S_LEN * D_MODEL];
__device__ __half g_Kh  [N_BC * T_LEN * D_MODEL];
__device__ __half g_Vh  [N_BC * T_LEN * D_MODEL];
__device__ __half g_AOh [N_BC * S_LEN * D_MODEL];
__device__ __half g_Wqh[D_MODEL * D_MODEL];
__device__ __half g_Wkh[D_MODEL * D_MODEL];
__device__ __half g_Wvh[D_MODEL * D_MODEL];
__device__ __half g_Woh[D_MODEL * D_MODEL];

// ================= helpers =================
__device__ __forceinline__ uint32_t smem_u32(const void* p) {
    uint32_t a;
    asm("{ .reg .u64 t; cvta.to.shared.u64 t, %1; cvt.u32.u64 %0, t; }" : "=r"(a) : "l"(p));
    return a;
}
__device__ __forceinline__ void ldm_x4(uint32_t* r, uint32_t addr) {
    asm volatile("ldmatrix.sync.aligned.m8n8.x4.shared.b16 {%0,%1,%2,%3}, [%4];"
        : "=r"(r[0]), "=r"(r[1]), "=r"(r[2]), "=r"(r[3]) : "r"(addr));
}
__device__ __forceinline__ void ldm_x4_t(uint32_t* r, uint32_t addr) {
    asm volatile("ldmatrix.sync.aligned.m8n8.x4.trans.shared.b16 {%0,%1,%2,%3}, [%4];"
        : "=r"(r[0]), "=r"(r[1]), "=r"(r[2]), "=r"(r[3]) : "r"(addr));
}
__device__ __forceinline__ void mma16816h(float* d, const uint32_t* a,
                                          uint32_t b0, uint32_t b1) {
    asm volatile(
        "mma.sync.aligned.m16n8k16.row.col.f32.f16.f16.f32 "
        "{%0,%1,%2,%3}, {%4,%5,%6,%7}, {%8,%9}, {%0,%1,%2,%3};"
        : "+f"(d[0]), "+f"(d[1]), "+f"(d[2]), "+f"(d[3])
        : "r"(a[0]), "r"(a[1]), "r"(a[2]), "r"(a[3]), "r"(b0), "r"(b1));
}
__device__ __forceinline__ void cp_async16(uint32_t dst, const void* src) {
    asm volatile("cp.async.cg.shared.global [%0], [%1], 16;" :: "r"(dst), "l"(src));
}
#define CP_COMMIT() asm volatile("cp.async.commit_group;" ::: "memory")
#define CP_WAIT(n)  asm volatile("cp.async.wait_group %0;" :: "n"(n) : "memory")

__device__ __forceinline__ uint32_t packh2(float a, float b) {
    __half2 h = __floats2half2_rn(a, b);
    return *(uint32_t*)&h;
}
__device__ __forceinline__ float ex2a(float x) {
    float y; asm("ex2.approx.f32 %0, %1;" : "=f"(y) : "f"(x)); return y;
}
__device__ __forceinline__ float rcpa(float x) {
    float y; asm("rcp.approx.f32 %0, %1;" : "=f"(y) : "f"(x)); return y;
}

// ================= fp32 -> fp16 convert =================
__global__ void f2h_kernel(const float* __restrict__ x, __half* __restrict__ y, int n4)
{
    int i = blockIdx.x * blockDim.x + threadIdx.x;
    if (i < n4) {
        float4 v = ((const float4*)x)[i];
        __half2* yp = (__half2*)y + i * 2;
        yp[0] = __floats2half2_rn(v.x, v.y);
        yp[1] = __floats2half2_rn(v.z, v.w);
    }
}

__global__ void f2h4_kernel(const float* __restrict__ x0, const float* __restrict__ x1,
                            const float* __restrict__ x2, const float* __restrict__ x3,
                            __half* __restrict__ y0, __half* __restrict__ y1,
                            __half* __restrict__ y2, __half* __restrict__ y3, int n4)
{
    const float* x; __half* y;
    switch (blockIdx.y) {
        case 0:  x = x0; y = y0; break;
        case 1:  x = x1; y = y1; break;
        case 2:  x = x2; y = y2; break;
        default: x = x3; y = y3; break;
    }
    int i = blockIdx.x * blockDim.x + threadIdx.x;
    if (i < n4) {
        float4 v = ((const float4*)x)[i];
        __half2* yp = (__half2*)y + i * 2;
        yp[0] = __floats2half2_rn(v.x, v.y);
        yp[1] = __floats2half2_rn(v.z, v.w);
    }
}

// ================= fp16 GEMM core (R10 winner): 128x128 CTA, 256 thr, warp 32x64 ===
#define LDA    72
#define ASTG   (128 * LDA)
#define STG2   (2 * ASTG)
#define GEMM_SMEM_BYTES (2 * STG2 * 2)   // 73728

template<bool HOUT>
__device__ __forceinline__ void gemm_core(
    const __half* __restrict__ A, const __half* __restrict__ B,
    const float* __restrict__ bias, void* __restrict__ Yv,
    int M, int N, int K, int bm, int bn, char* smemc)
{
    const uint32_t sbase = smem_u32(smemc);
    const int tid  = threadIdx.x;
    const int wid  = tid >> 5;
    const int lane = tid & 31;
    const int wm   = wid & 3;
    const int wn   = wid >> 2;
    const int xrow = lane & 15;
    const int xk   = (lane >> 4) << 3;

    const int crow = tid >> 3;              // 0..31
    const int ccol = (tid & 7) << 3;
    const __half* aptr[4];
    const __half* bptr[4];
    uint32_t soff[4];
    #pragma unroll
    for (int t = 0; t < 4; ++t) {
        int row = crow + t * 32;
        aptr[t] = A + (size_t)min(bm + row, M - 1) * K + ccol;
        bptr[t] = B + (size_t)(bn + row) * K + ccol;
        soff[t] = (uint32_t)(row * LDA + ccol) * 2;
    }

    float acc[2][8][4];
    #pragma unroll
    for (int i = 0; i < 2; ++i)
        #pragma unroll
        for (int j = 0; j < 8; ++j)
            #pragma unroll
            for (int q = 0; q < 4; ++q) acc[i][j][q] = 0.f;

    const int NIT = K / 64;   // 24

    auto issue = [&](int it) {
        const int s  = it & 1;
        const int k0 = it * 64;
        uint32_t sa = sbase + (uint32_t)s * STG2 * 2;
        uint32_t sb = sa + ASTG * 2;
        #pragma unroll
        for (int t = 0; t < 4; ++t) {
            cp_async16(sa + soff[t], aptr[t] + k0);
            cp_async16(sb + soff[t], bptr[t] + k0);
        }
    };

    issue(0); CP_COMMIT();

    for (int it = 0; it < NIT; ++it) {
        CP_WAIT(0);
        __syncthreads();
        if (it + 1 < NIT) { issue(it + 1); CP_COMMIT(); }

        const uint32_t sa = sbase + (uint32_t)(it & 1) * STG2 * 2;
        const uint32_t sb = sa + ASTG * 2;

        #pragma unroll
        for (int kk = 0; kk < 4; ++kk) {
            const int k0 = kk * 16;
            uint32_t af[2][4];
            #pragma unroll
            for (int mf = 0; mf < 2; ++mf)
                ldm_x4(af[mf], sa + (uint32_t)((wm * 32 + mf * 16 + xrow) * LDA + k0 + xk) * 2);
            uint32_t bf[4][4];
            #pragma unroll
            for (int nf4 = 0; nf4 < 4; ++nf4)
                ldm_x4(bf[nf4], sb + (uint32_t)((wn * 64 + nf4 * 16 + xrow) * LDA + k0 + xk) * 2);
            #pragma unroll
            for (int nf4 = 0; nf4 < 4; ++nf4) {
                #pragma unroll
                for (int mf = 0; mf < 2; ++mf) {
                    mma16816h(acc[mf][nf4 * 2],     af[mf], bf[nf4][0], bf[nf4][2]);
                    mma16816h(acc[mf][nf4 * 2 + 1], af[mf], bf[nf4][1], bf[nf4][3]);
                }
            }
        }
    }

    const int g  = lane >> 2;
    const int t2 = (lane & 3) << 1;
    #pragma unroll
    for (int mf = 0; mf < 2; ++mf) {
        int r0 = bm + wm * 32 + mf * 16 + g;
        #pragma unroll
        for (int nf = 0; nf < 8; ++nf) {
            int col = bn + wn * 64 + nf * 8 + t2;
            float bv0 = bias[col], bv1 = bias[col + 1];
            float v00 = acc[mf][nf][0] + bv0, v01 = acc[mf][nf][1] + bv1;
            float v10 = acc[mf][nf][2] + bv0, v11 = acc[mf][nf][3] + bv1;
            if (HOUT) {
                __half* Y = (__half*)Yv;
                if (r0 < M)     *(__half2*)(Y + (size_t)r0 * N + col)       = __floats2half2_rn(v00, v01);
                if (r0 + 8 < M) *(__half2*)(Y + (size_t)(r0 + 8) * N + col) = __floats2half2_rn(v10, v11);
            } else {
                float* Y = (float*)Yv;
                if (r0 < M)     *(float2*)(Y + (size_t)r0 * N + col)       = make_float2(v00, v01);
                if (r0 + 8 < M) *(float2*)(Y + (size_t)(r0 + 8) * N + col) = make_float2(v10, v11);
            }
        }
    }
}

#define QCTAS  3072
#define KVCTAS 120

__global__ __launch_bounds__(256, 2)
void qkv_gemm(const __half* __restrict__ HSh, const __half* __restrict__ EHSh,
              const __half* __restrict__ Wq, const float* __restrict__ bq, __half* __restrict__ Qh,
              const __half* __restrict__ Wk, const float* __restrict__ bk, __half* __restrict__ Kh,
              const __half* __restrict__ Wv, const float* __restrict__ bv, __half* __restrict__ Vh)
{
    extern __shared__ char smemc[];
    int id = blockIdx.x;
    const __half* A; const __half* B; const float* bias; __half* Y; int M, bm, bn;
    if (id < QCTAS) {
        A = HSh; B = Wq; bias = bq; Y = Qh; M = N_BC * S_LEN;
        bm = (id / 12) * 128; bn = (id % 12) * 128;
    } else if (id < QCTAS + KVCTAS) {
        int r = id - QCTAS;
        A = EHSh; B = Wk; bias = bk; Y = Kh; M = N_BC * T_LEN;
        bm = (r / 12) * 128; bn = (r % 12) * 128;
    } else {
        int r = id - QCTAS - KVCTAS;
        A = EHSh; B = Wv; bias = bv; Y = Vh; M = N_BC * T_LEN;
        bm = (r / 12) * 128; bn = (r % 12) * 128;
    }
    gemm_core<true>(A, B, bias, Y, M, D_MODEL, D_MODEL, bm, bn, smemc);
}

__global__ __launch_bounds__(256, 2)
void o_gemm(const __half* __restrict__ A, const __half* __restrict__ B,
            const float* __restrict__ bias, float* __restrict__ Y)
{
    extern __shared__ char smemc[];
    int id = blockIdx.x;
    gemm_core<false>(A, B, bias, Y, N_BC * S_LEN, D_MODEL, D_MODEL,
                     (id / 12) * 128, (id % 12) * 128, smemc);
}

// ================= register-softmax HMMA attention (s-tile 128) ====================
// CTA: 256 threads (8 warps), s-tile 128. Warp = 16 s-rows x full d=64, all 4 comps.
// K/V restaging halved vs s-tile 64.
#define QST 72
#define KST 72
#define KV_MAT   (4 * 32 * KST * 2)              // 18432 B
#define KV_STAGE (2 * KV_MAT)                    // 36864 B (K + V)
#define ATTN_SMEM_BYTES (4 * 128 * QST * 2 + 2 * KV_STAGE)  // 147456

#define SM_SCALE 0.1803368801f

__global__ __launch_bounds__(256, 1)
void attn_reg(const __half* __restrict__ Q, const __half* __restrict__ K,
              const __half* __restrict__ V, __half* __restrict__ O)
{
    extern __shared__ char smemc[];
    __half* qb = (__half*)smemc;                 // [4][128][QST]
    const uint32_t qbu = smem_u32(qb);
    const uint32_t kvu = qbu + 4 * 128 * QST * 2;

    const int tid  = threadIdx.x;
    const int wid  = tid >> 5;
    const int lane = tid & 31;
    const int b    = blockIdx.z;
    const int h    = blockIdx.y;
    const int s0   = blockIdx.x * 128;

    const int sbase = wid * 16;          // 0..112
    const int xrow  = lane & 15;
    const int xk    = (lane >> 4) << 3;
    const int g     = lane >> 2;
    const int q2    = (lane & 3) << 1;

    // ---- load Q tile: 4c x 128s x 64d = 4096 uint4, 16 per thread ----
    #pragma unroll
    for (int it = 0; it < 16; ++it) {
        int i  = tid + it * 256;
        int cc = i >> 10, r = i & 1023, si = r >> 3, d8 = (r & 7) << 3;
        const __half* gp = Q + ((size_t)(cc * N_B + b) * S_LEN + s0 + si) * D_MODEL + h * DH + d8;
        *(uint4*)(qb + (cc * 128 + si) * QST + d8) = *(const uint4*)gp;
    }

    const int NCH = (T_LEN + 31) / 32;   // 5

    auto issue = [&](int ch) {
        const int t0 = ch * 32;
        const uint32_t st = kvu + (uint32_t)(ch & 1) * KV_STAGE;
        #pragma unroll
        for (int it = 0; it < 4; ++it) {
            int i  = tid + it * 256;
            int cc = i >> 8, r = i & 255, tj = r >> 3, d8 = (r & 7) << 3;
            int t = min(t0 + tj, T_LEN - 1);     // clamp; weights zeroed for t>=T_LEN
            size_t go = ((size_t)(cc * N_B + b) * T_LEN + t) * D_MODEL + h * DH + d8;
            uint32_t so = (uint32_t)((cc * 32 + tj) * KST + d8) * 2;
            cp_async16(st + so, K + go);
            cp_async16(st + KV_MAT + so, V + go);
        }
    };

    issue(0); CP_COMMIT();
    issue(1); CP_COMMIT();

    float oacc[4][8][4];
    #pragma unroll
    for (int c = 0; c < 4; ++c)
        #pragma unroll
        for (int j = 0; j < 8; ++j)
            #pragma unroll
            for (int e = 0; e < 4; ++e) oacc[c][j][e] = 0.f;
    float rsum[2][4];
    #pragma unroll
    for (int r = 0; r < 2; ++r)
        #pragma unroll
        for (int c = 0; c < 4; ++c) rsum[r][c] = 0.f;

    for (int ch = 0; ch < NCH; ++ch) {
        if (ch == NCH - 1) { CP_WAIT(0); } else { CP_WAIT(1); }
        __syncthreads();

        const uint32_t kbu = kvu + (uint32_t)(ch & 1) * KV_STAGE;
        const uint32_t vbu = kbu + KV_MAT;

        // ---- scores: 16s x 32t per warp, all 4 components ----
        float sacc[4][4][4];
        #pragma unroll
        for (int c = 0; c < 4; ++c)
            #pragma unroll
            for (int j = 0; j < 4; ++j)
                #pragma unroll
                for (int e = 0; e < 4; ++e) sacc[c][j][e] = 0.f;

        #pragma unroll
        for (int c = 0; c < 4; ++c) {
            #pragma unroll
            for (int kk = 0; kk < 4; ++kk) {
                uint32_t af[4];
                ldm_x4(af, qbu + (uint32_t)((c * 128 + sbase + xrow) * QST + kk * 16 + xk) * 2);
                #pragma unroll
                for (int nf16 = 0; nf16 < 2; ++nf16) {
                    uint32_t bf[4];
                    ldm_x4(bf, kbu + (uint32_t)((c * 32 + nf16 * 16 + xrow) * KST + kk * 16 + xk) * 2);
                    mma16816h(sacc[c][nf16 * 2],     af, bf[0], bf[2]);
                    mma16816h(sacc[c][nf16 * 2 + 1], af, bf[1], bf[3]);
                }
            }
        }

        // ---- register softmax (e3-baseline) + AV ----
        #pragma unroll
        for (int kk = 0; kk < 2; ++kk) {
            uint32_t wf[4][4];
            #pragma unroll
            for (int jh = 0; jh < 2; ++jh) {
                const int j = kk * 2 + jh;
                float wt[4][4];
                #pragma unroll
                for (int e = 0; e < 4; ++e) {
                    int col = ch * 32 + j * 8 + q2 + (e & 1);
                    float t3 = sacc[3][j][e] * SM_SCALE;
                    float e0 = ex2a(fmaf(sacc[0][j][e], SM_SCALE, -t3));
                    float e1 = ex2a(fmaf(sacc[1][j][e], SM_SCALE, -t3));
                    float e2 = ex2a(fmaf(sacc[2][j][e], SM_SCALE, -t3));
                    float inv = (col < T_LEN) ? rcpa(e0 + e1 + e2 + 1.f) : 0.f;
                    e0 *= inv; e1 *= inv; e2 *= inv;
                    int rr = e >> 1;
                    rsum[rr][0] += e0; rsum[rr][1] += e1;
                    rsum[rr][2] += e2; rsum[rr][3] += inv;
                    wt[0][e] = e0; wt[1][e] = e1; wt[2][e] = e2; wt[3][e] = inv;
                }
                #pragma unroll
                for (int c = 0; c < 4; ++c) {
                    wf[c][jh * 2 + 0] = packh2(wt[c][0], wt[c][1]);
                    wf[c][jh * 2 + 1] = packh2(wt[c][2], wt[c][3]);
                }
            }
            #pragma unroll
            for (int c = 0; c < 4; ++c) {
                #pragma unroll
                for (int nf16 = 0; nf16 < 4; ++nf16) {
                    uint32_t bf[4];
                    ldm_x4_t(bf, vbu + (uint32_t)((c * 32 + kk * 16 + xrow) * KST + nf16 * 16 + xk) * 2);
                    mma16816h(oacc[c][nf16 * 2],     wf[c], bf[0], bf[1]);
                    mma16816h(oacc[c][nf16 * 2 + 1], wf[c], bf[2], bf[3]);
                }
            }
        }
        __syncthreads();
        if (ch + 2 < NCH) { issue(ch + 2); CP_COMMIT(); }
    }

    #pragma unroll
    for (int x = 1; x <= 2; x <<= 1)
        #pragma unroll
        for (int r = 0; r < 2; ++r)
            #pragma unroll
            for (int c = 0; c < 4; ++c)
                rsum[r][c] += __shfl_xor_sync(0xffffffffu, rsum[r][c], x);

    #pragma unroll
    for (int c = 0; c < 4; ++c) {
        float inv0 = 1.f / (rsum[0][c] + 1e-8f);
        float inv1 = 1.f / (rsum[1][c] + 1e-8f);
        int row0 = s0 + sbase + g;
        __half* gp0 = O + ((size_t)(c * N_B + b) * S_LEN + row0) * D_MODEL + h * DH + q2;
        __half* gp1 = gp0 + (size_t)8 * D_MODEL;
        #pragma unroll
        for (int j = 0; j < 8; ++j) {
            *(__half2*)(gp0 + j * 8) = __floats2half2_rn(oacc[c][j][0] * inv0, oacc[c][j][1] * inv0);
            *(__half2*)(gp1 + j * 8) = __floats2half2_rn(oacc[c][j][2] * inv1, oacc[c][j][3] * inv1);
        }
    }
}

// ---------------- launch ----------------
extern "C" void kernel_launch(void* const* d_in, const int* in_sizes, int n_in,
                              void* d_out, int out_size)
{
    const float* HS  = (const float*)d_in[0];
    const float* EHS = (const float*)d_in[1];
    const float* Wq  = (const float*)d_in[2];
    const float* bq  = (const float*)d_in[3];
    const float* Wk  = (const float*)d_in[4];
    const float* bk  = (const float*)d_in[5];
    const float* Wv  = (const float*)d_in[6];
    const float* bv  = (const float*)d_in[7];
    const float* Wo  = (const float*)d_in[8];
    const float* bo  = (const float*)d_in[9];
    float* out = (float*)d_out;

    __half *pHSh, *pEHSh, *pQh, *pKh, *pVh, *pAOh, *pWqh, *pWkh, *pWvh, *pWoh;
    cudaGetSymbolAddress((void**)&pHSh,  g_HSh);
    cudaGetSymbolAddress((void**)&pEHSh, g_EHSh);
    cudaGetSymbolAddress((void**)&pQh,   g_Qh);
    cudaGetSymbolAddress((void**)&pKh,   g_Kh);
    cudaGetSymbolAddress((void**)&pVh,   g_Vh);
    cudaGetSymbolAddress((void**)&pAOh,  g_AOh);
    cudaGetSymbolAddress((void**)&pWqh,  g_Wqh);
    cudaGetSymbolAddress((void**)&pWkh,  g_Wkh);
    cudaGetSymbolAddress((void**)&pWvh,  g_Wvh);
    cudaGetSymbolAddress((void**)&pWoh,  g_Woh);

    cudaFuncSetAttribute(qkv_gemm, cudaFuncAttributeMaxDynamicSharedMemorySize, GEMM_SMEM_BYTES);
    cudaFuncSetAttribute(o_gemm,   cudaFuncAttributeMaxDynamicSharedMemorySize, GEMM_SMEM_BYTES);
    cudaFuncSetAttribute(attn_reg, cudaFuncAttributeMaxDynamicSharedMemorySize, ATTN_SMEM_BYTES);

    const int nHS = N_BC * S_LEN * D_MODEL / 4;
    const int nEH = N_BC * T_LEN * D_MODEL / 4;
    const int nW  = D_MODEL * D_MODEL / 4;
    f2h_kernel<<<(nHS + 255) / 256, 256>>>(HS,  pHSh,  nHS);
    f2h_kernel<<<(nEH + 255) / 256, 256>>>(EHS, pEHSh, nEH);
    f2h4_kernel<<<dim3((nW + 255) / 256, 4), 256>>>(Wq, Wk, Wv, Wo,
                                                    pWqh, pWkh, pWvh, pWoh, nW);

    // merged Q + K + V projections (fp16 out), one launch, 256-thread core
    qkv_gemm<<<QCTAS + 2 * KVCTAS, 256, GEMM_SMEM_BYTES>>>(
        pHSh, pEHSh, pWqh, bq, pQh, pWkh, bk, pKh, pWvh, bv, pVh);
    // register-softmax HMMA attention, s-tile 128 (halved K/V restaging)
    attn_reg<<<dim3(S_LEN / 128, N_H, N_B), 256, ATTN_SMEM_BYTES>>>(pQh, pKh, pVh, pAOh);
    // output projection (fp32 output into d_out)
    o_gemm<<<QCTAS, 256, GEMM_SMEM_BYTES>>>(pAOh, pWoh, bo, out);
}